// round 10
// baseline (speedup 1.0000x reference)
#include <cuda_runtime.h>
#include <math.h>

#define B_    16
#define C_    256
#define HIDE_ 128
#define HW_   16384
#define HW4_  4096            // float4 per row
#define ROWS_ (B_*C_)         // 4096
#define LAG_  2               // reducers may run at most LAG_ batches ahead of scalers

__device__ float g_mean[ROWS_];
__device__ float g_gate[ROWS_];
__device__ int   g_red_cnt[B_];           // reducer arrivals (self-reset by gate CTA)
__device__ int   g_scl_cnt[B_];           // scaler arrivals  (self-reset by last scaler)
__device__ volatile int g_flag_gate[B_];  // gate(b) ready    (set by gate CTA, reset by last scaler)
__device__ volatile int g_flag_scl[B_];   // scale(b) done    (set by last scaler b<B-LAG, reset by gate CTA of b+LAG)

__global__ void __launch_bounds__(256)
k_pipeline(const float* __restrict__ x,
           const float* __restrict__ w1,
           const float* __restrict__ w2p,
           const float* __restrict__ w3p,
           const float* __restrict__ w4,
           const float* __restrict__ A2,
           float* __restrict__ out) {
    const int t = threadIdx.x;

    if (blockIdx.x < C_) {
        // ========================= REDUCER CTA (one row r of every batch) =========================
        const int r = blockIdx.x;
        __shared__ __align__(16) float mean_s[C_];
        __shared__ __align__(16) float y_s[HIDE_];
        __shared__ __align__(16) float z_s[HIDE_];
        __shared__ __align__(16) float red[256];
        __shared__ float sm[8];
        __shared__ int   last_s;

        for (int b = 0; b < B_; ++b) {
            // throttle: stay at most LAG_ batches ahead of the scalers
            if (b >= LAG_) {
                if (t == 0) {
                    while (g_flag_scl[b - LAG_] == 0) __nanosleep(64);
                }
                __syncthreads();
            }

            const int row = b * C_ + r;
            const float4* xr = reinterpret_cast<const float4*>(x) + (size_t)row * HW4_;
            float s = 0.f;
            #pragma unroll
            for (int i = 0; i < 16; ++i) {
                float4 v = xr[t + i * 256];          // evict-normal: leave resident in L2
                s += (v.x + v.y) + (v.z + v.w);
            }
            #pragma unroll
            for (int off = 16; off > 0; off >>= 1)
                s += __shfl_down_sync(0xffffffffu, s, off);
            int lane = t & 31, wid = t >> 5;
            if (lane == 0) sm[wid] = s;
            __syncthreads();
            if (t == 0) {
                float tot = 0.f;
                #pragma unroll
                for (int w = 0; w < 8; ++w) tot += sm[w];
                g_mean[row] = tot * (1.0f / (float)HW_);
                __threadfence();
                int old = atomicAdd(&g_red_cnt[b], 1);
                last_s = (old == C_ - 1);
            }
            __syncthreads();

            if (last_s) {
                // ---- gate for batch b (runs in exactly one CTA) ----
                __threadfence();
                mean_s[t] = __ldcg(&g_mean[b * C_ + t]);
                __syncthreads();

                const float w2 = *w2p;
                const float w3 = *w3p;

                if (t < HIDE_) {
                    const float4* wr = reinterpret_cast<const float4*>(w1 + (size_t)t * C_);
                    const float4* ms = reinterpret_cast<const float4*>(mean_s);
                    float acc = 0.f;
                    #pragma unroll 16
                    for (int k = 0; k < C_ / 4; ++k) {
                        float4 w = wr[k];
                        float4 m = ms[k];
                        acc = fmaf(m.x, w.x, acc);
                        acc = fmaf(m.y, w.y, acc);
                        acc = fmaf(m.z, w.z, acc);
                        acc = fmaf(m.w, w.w, acc);
                    }
                    y_s[t] = acc;
                }
                __syncthreads();

                float v = (t < HIDE_) ? w2 * y_s[t] : -INFINITY;
                red[t] = v;
                __syncthreads();
                #pragma unroll
                for (int off = 128; off > 0; off >>= 1) {
                    if (t < off) red[t] = fmaxf(red[t], red[t + off]);
                    __syncthreads();
                }
                float m = red[0];
                __syncthreads();
                float e = (t < HIDE_) ? __expf(v - m) : 0.f;
                red[t] = e;
                __syncthreads();
                #pragma unroll
                for (int off = 128; off > 0; off >>= 1) {
                    if (t < off) red[t] += red[t + off];
                    __syncthreads();
                }
                float inv_sum = 1.0f / red[0];
                __syncthreads();

                if (t < HIDE_) {
                    float acc = 0.f;
                    #pragma unroll 8
                    for (int k = 0; k < HIDE_; ++k)
                        acc = fmaf(y_s[k], A2[(size_t)k * HIDE_ + t], acc);
                    float y2 = y_s[t] * (e * inv_sum) + acc;
                    z_s[t] = fmaxf(w3 * y2, 0.f);
                }
                __syncthreads();

                {
                    const float4* wr = reinterpret_cast<const float4*>(w4 + (size_t)t * HIDE_);
                    const float4* zs = reinterpret_cast<const float4*>(z_s);
                    float acc = 0.f;
                    #pragma unroll 16
                    for (int k = 0; k < HIDE_ / 4; ++k) {
                        float4 w = wr[k];
                        float4 z = zs[k];
                        acc = fmaf(z.x, w.x, acc);
                        acc = fmaf(z.y, w.y, acc);
                        acc = fmaf(z.z, w.z, acc);
                        acc = fmaf(z.w, w.w, acc);
                    }
                    g_gate[b * C_ + t] = 1.0f / (1.0f + __expf(-acc));
                }
                __syncthreads();
                if (t == 0) {
                    g_red_cnt[b] = 0;                 // self-reset (all arrivals counted)
                    if (b >= LAG_) g_flag_scl[b - LAG_] = 0;  // consumed by all reducers of batch b
                    __threadfence();                  // release: gate before flag
                    g_flag_gate[b] = 1;
                }
            }
        }
    } else {
        // ========================= SCALER CTA (one row r of every batch) =========================
        const int r = blockIdx.x - C_;

        for (int b = 0; b < B_; ++b) {
            if (t == 0) {
                while (g_flag_gate[b] == 0) __nanosleep(64);
                __threadfence();          // acquire before reading g_gate
            }
            __syncthreads();

            const int row = b * C_ + r;
            float gt = __ldcg(&g_gate[row]);
            const float4* x4 = reinterpret_cast<const float4*>(x) + (size_t)row * HW4_;
            float4* o4 = reinterpret_cast<float4*>(out) + (size_t)row * HW4_;
            #pragma unroll
            for (int i = 0; i < 16; ++i) {
                int idx = t + i * 256;
                float4 v = __ldcg(&x4[idx]);   // expected L2 hit (reduced one stage ago)
                v.x *= gt; v.y *= gt; v.z *= gt; v.w *= gt;
                __stcs(&o4[idx], v);           // evict-first: don't displace x
            }

            if (t == 0) {
                int old = atomicAdd(&g_scl_cnt[b], 1);
                if (old == C_ - 1) {                     // last scaler of batch b
                    g_scl_cnt[b] = 0;
                    g_flag_gate[b] = 0;
                    __threadfence();
                    if (b < B_ - LAG_) g_flag_scl[b] = 1;  // unblock reducers of b+LAG
                }
            }
            __syncthreads();   // keep CTA together before next stage
        }
    }
}

extern "C" void kernel_launch(void* const* d_in, const int* in_sizes, int n_in,
                              void* d_out, int out_size) {
    const float* x  = (const float*)d_in[0];
    const float* w1 = (const float*)d_in[1];
    const float* w2 = (const float*)d_in[2];
    const float* w3 = (const float*)d_in[3];
    const float* w4 = (const float*)d_in[4];
    const float* A2 = (const float*)d_in[5];
    float* out = (float*)d_out;

    k_pipeline<<<2 * C_, 256>>>(x, w1, w2, w3, w4, A2, out);
}

// round 11
// speedup vs baseline: 3.0267x; 3.0267x over previous
#include <cuda_runtime.h>
#include <math.h>

// Shapes (fixed by the problem)
#define B_  16
#define C_  256
#define HIDE_ 128
#define HW_ 16384          // 128*128
#define HW4_ 4096          // float4 per row
#define ROWS_ (B_*C_)      // 4096

__device__ float g_mean[ROWS_];
__device__ float g_gate[ROWS_];

// ---------------- Kernel 1: per-(b,c) mean over H*W (pure streaming, no sync machinery) ----------------
__global__ void __launch_bounds__(256) k_reduce(const float* __restrict__ x) {
    int row = blockIdx.x;
    const float4* xr = reinterpret_cast<const float4*>(x) + (size_t)row * HW4_;
    float s = 0.f;
    #pragma unroll 4
    for (int i = threadIdx.x; i < HW4_; i += 256) {
        float4 v = xr[i];
        s += (v.x + v.y) + (v.z + v.w);
    }
    #pragma unroll
    for (int off = 16; off > 0; off >>= 1)
        s += __shfl_down_sync(0xffffffffu, s, off);
    __shared__ float sm[8];
    int lane = threadIdx.x & 31, wid = threadIdx.x >> 5;
    if (lane == 0) sm[wid] = s;
    __syncthreads();
    if (wid == 0) {
        s = (lane < 8) ? sm[lane] : 0.f;
        #pragma unroll
        for (int off = 4; off > 0; off >>= 1)
            s += __shfl_down_sync(0xffffffffu, s, off);
        if (lane == 0) g_mean[row] = s * (1.0f / (float)HW_);
    }
}

// ---------------- Kernel 2: gate (one block per batch, 16 blocks) ----------------
__global__ void __launch_bounds__(256) k_gate(const float* __restrict__ w1,
                                              const float* __restrict__ w2p,
                                              const float* __restrict__ w3p,
                                              const float* __restrict__ w4,
                                              const float* __restrict__ A2) {
    int b = blockIdx.x;
    int t = threadIdx.x;
    __shared__ __align__(16) float mean_s[C_];
    __shared__ __align__(16) float y_s[HIDE_];
    __shared__ __align__(16) float z_s[HIDE_];
    __shared__ __align__(16) float red[256];

    mean_s[t] = g_mean[b * C_ + t];
    __syncthreads();

    const float w2 = *w2p;
    const float w3 = *w3p;

    // conv1: y[j] = dot(mean, w1[j,:])
    if (t < HIDE_) {
        const float4* wr = reinterpret_cast<const float4*>(w1 + (size_t)t * C_);
        const float4* ms = reinterpret_cast<const float4*>(mean_s);
        float acc = 0.f;
        #pragma unroll 16
        for (int k = 0; k < C_ / 4; ++k) {
            float4 w = wr[k];
            float4 m = ms[k];
            acc = fmaf(m.x, w.x, acc);
            acc = fmaf(m.y, w.y, acc);
            acc = fmaf(m.z, w.z, acc);
            acc = fmaf(m.w, w.w, acc);
        }
        y_s[t] = acc;
    }
    __syncthreads();

    // softmax over HIDE of (w2 * y)
    float v = (t < HIDE_) ? w2 * y_s[t] : -INFINITY;
    red[t] = v;
    __syncthreads();
    #pragma unroll
    for (int off = 128; off > 0; off >>= 1) {
        if (t < off) red[t] = fmaxf(red[t], red[t + off]);
        __syncthreads();
    }
    float m = red[0];
    __syncthreads();
    float e = (t < HIDE_) ? __expf(v - m) : 0.f;
    red[t] = e;
    __syncthreads();
    #pragma unroll
    for (int off = 128; off > 0; off >>= 1) {
        if (t < off) red[t] += red[t + off];
        __syncthreads();
    }
    float inv_sum = 1.0f / red[0];
    __syncthreads();

    // y2 = y*softmax + y@A2 ; z = relu(w3*y2)
    if (t < HIDE_) {
        float acc = 0.f;
        #pragma unroll 8
        for (int k = 0; k < HIDE_; ++k) acc = fmaf(y_s[k], A2[(size_t)k * HIDE_ + t], acc);
        float y2 = y_s[t] * (e * inv_sum) + acc;
        z_s[t] = fmaxf(w3 * y2, 0.f);
    }
    __syncthreads();

    // conv4 + sigmoid
    {
        const float4* wr = reinterpret_cast<const float4*>(w4 + (size_t)t * HIDE_);
        const float4* zs = reinterpret_cast<const float4*>(z_s);
        float acc = 0.f;
        #pragma unroll 16
        for (int k = 0; k < HIDE_ / 4; ++k) {
            float4 w = wr[k];
            float4 z = zs[k];
            acc = fmaf(z.x, w.x, acc);
            acc = fmaf(z.y, w.y, acc);
            acc = fmaf(z.z, w.z, acc);
            acc = fmaf(z.w, w.w, acc);
        }
        g_gate[b * C_ + t] = 1.0f / (1.0f + __expf(-acc));
    }
}

// ---------------- Kernel 3: out = x * gate (R4's measured-best streaming form) ----------------
__global__ void __launch_bounds__(256) k_scale(const float* __restrict__ x,
                                               float* __restrict__ out) {
    int row = blockIdx.x;
    float g = __ldg(&g_gate[row]);
    const float4* x4 = reinterpret_cast<const float4*>(x) + (size_t)row * HW4_;
    float4* o4 = reinterpret_cast<float4*>(out) + (size_t)row * HW4_;
    #pragma unroll 16
    for (int i = threadIdx.x; i < HW4_; i += 256) {
        float4 v = __ldcs(&x4[i]);
        v.x *= g; v.y *= g; v.z *= g; v.w *= g;
        __stcs(&o4[i], v);
    }
}

extern "C" void kernel_launch(void* const* d_in, const int* in_sizes, int n_in,
                              void* d_out, int out_size) {
    const float* x  = (const float*)d_in[0];
    const float* w1 = (const float*)d_in[1];
    const float* w2 = (const float*)d_in[2];
    const float* w3 = (const float*)d_in[3];
    const float* w4 = (const float*)d_in[4];
    const float* A2 = (const float*)d_in[5];
    float* out = (float*)d_out;

    k_reduce<<<ROWS_, 256>>>(x);
    k_gate<<<B_, 256>>>(w1, w2, w3, w4, A2);
    k_scale<<<ROWS_, 256>>>(x, out);
}

// round 12
// speedup vs baseline: 3.1965x; 1.0561x over previous
#include <cuda_runtime.h>
#include <math.h>

#define B_  16
#define C_  256
#define HIDE_ 128
#define HW_ 16384          // 128*128
#define HW4_ 4096          // float4 per row
#define ROWS_ (B_*C_)      // 4096

__device__ float g_mean[ROWS_];
__device__ float g_gate[ROWS_];

__device__ __forceinline__ void l2_prefetch(const void* p) {
    asm volatile("prefetch.global.L2 [%0];" :: "l"(p));
}

// ---------------- Kernel 1: per-(b,c) mean; trigger PDL as soon as mean is written ----------------
__global__ void __launch_bounds__(256) k_reduce(const float* __restrict__ x) {
    int row = blockIdx.x;
    const float4* xr = reinterpret_cast<const float4*>(x) + (size_t)row * HW4_;
    float s = 0.f;
    #pragma unroll 4
    for (int i = threadIdx.x; i < HW4_; i += 256) {
        float4 v = xr[i];
        s += (v.x + v.y) + (v.z + v.w);
    }
    #pragma unroll
    for (int off = 16; off > 0; off >>= 1)
        s += __shfl_down_sync(0xffffffffu, s, off);
    __shared__ float sm[8];
    int lane = threadIdx.x & 31, wid = threadIdx.x >> 5;
    if (lane == 0) sm[wid] = s;
    __syncthreads();
    if (wid == 0) {
        s = (lane < 8) ? sm[lane] : 0.f;
        #pragma unroll
        for (int off = 4; off > 0; off >>= 1)
            s += __shfl_down_sync(0xffffffffu, s, off);
        if (lane == 0) {
            g_mean[row] = s * (1.0f / (float)HW_);
            __threadfence();
        }
    }
    cudaTriggerProgrammaticLaunchCompletion();
}

// ---------------- Kernel 2: gate. Launched via PDL; prefetches weights BEFORE the sync ----------------
__global__ void __launch_bounds__(256) k_gate(const float* __restrict__ w1,
                                              const float* __restrict__ w2p,
                                              const float* __restrict__ w3p,
                                              const float* __restrict__ w4,
                                              const float* __restrict__ A2) {
    int b = blockIdx.x;
    int t = threadIdx.x;
    __shared__ __align__(16) float mean_s[C_];
    __shared__ __align__(16) float y_s[HIDE_];
    __shared__ __align__(16) float z_s[HIDE_];
    __shared__ __align__(16) float red[256];

    // ---- pre-sync: warm L2 with all weights while k_reduce still runs ----
    // w1: 128*256 floats = 1024 lines; w4: 1024 lines; A2: 512 lines. 10 lines/thread.
    {
        const char* pw1 = (const char*)w1;
        const char* pw4 = (const char*)w4;
        const char* pa2 = (const char*)A2;
        #pragma unroll
        for (int i = 0; i < 4; ++i) l2_prefetch(pw1 + (t + i * 256) * 128);
        #pragma unroll
        for (int i = 0; i < 4; ++i) l2_prefetch(pw4 + (t + i * 256) * 128);
        #pragma unroll
        for (int i = 0; i < 2; ++i) l2_prefetch(pa2 + (t + i * 256) * 128);
    }

    cudaGridDependencySynchronize();   // wait: all k_reduce CTAs triggered (means written)

    mean_s[t] = g_mean[b * C_ + t];
    __syncthreads();

    const float w2 = *w2p;
    const float w3 = *w3p;

    // conv1: y[j] = dot(mean, w1[j,:])
    if (t < HIDE_) {
        const float4* wr = reinterpret_cast<const float4*>(w1 + (size_t)t * C_);
        const float4* ms = reinterpret_cast<const float4*>(mean_s);
        float acc = 0.f;
        #pragma unroll 16
        for (int k = 0; k < C_ / 4; ++k) {
            float4 w = wr[k];
            float4 m = ms[k];
            acc = fmaf(m.x, w.x, acc);
            acc = fmaf(m.y, w.y, acc);
            acc = fmaf(m.z, w.z, acc);
            acc = fmaf(m.w, w.w, acc);
        }
        y_s[t] = acc;
    }
    __syncthreads();

    // softmax over HIDE of (w2 * y)
    float v = (t < HIDE_) ? w2 * y_s[t] : -INFINITY;
    red[t] = v;
    __syncthreads();
    #pragma unroll
    for (int off = 128; off > 0; off >>= 1) {
        if (t < off) red[t] = fmaxf(red[t], red[t + off]);
        __syncthreads();
    }
    float m = red[0];
    __syncthreads();
    float e = (t < HIDE_) ? __expf(v - m) : 0.f;
    red[t] = e;
    __syncthreads();
    #pragma unroll
    for (int off = 128; off > 0; off >>= 1) {
        if (t < off) red[t] += red[t + off];
        __syncthreads();
    }
    float inv_sum = 1.0f / red[0];
    __syncthreads();

    // y2 = y*softmax + y@A2 ; z = relu(w3*y2)
    if (t < HIDE_) {
        float acc = 0.f;
        #pragma unroll 8
        for (int k = 0; k < HIDE_; ++k) acc = fmaf(y_s[k], A2[(size_t)k * HIDE_ + t], acc);
        float y2 = y_s[t] * (e * inv_sum) + acc;
        z_s[t] = fmaxf(w3 * y2, 0.f);
    }
    __syncthreads();

    // conv4 + sigmoid
    {
        const float4* wr = reinterpret_cast<const float4*>(w4 + (size_t)t * HIDE_);
        const float4* zs = reinterpret_cast<const float4*>(z_s);
        float acc = 0.f;
        #pragma unroll 16
        for (int k = 0; k < HIDE_ / 4; ++k) {
            float4 w = wr[k];
            float4 z = zs[k];
            acc = fmaf(z.x, w.x, acc);
            acc = fmaf(z.y, w.y, acc);
            acc = fmaf(z.z, w.z, acc);
            acc = fmaf(z.w, w.w, acc);
        }
        g_gate[b * C_ + t] = 1.0f / (1.0f + __expf(-acc));
        __threadfence();
    }
    cudaTriggerProgrammaticLaunchCompletion();
}

// ---------------- Kernel 3: out = x * gate. PDL: x loads issued BEFORE the dependency sync ----------------
__global__ void __launch_bounds__(256) k_scale(const float* __restrict__ x,
                                               float* __restrict__ out) {
    int row = blockIdx.x;
    const float4* x4 = reinterpret_cast<const float4*>(x) + (size_t)row * HW4_;
    float4* o4 = reinterpret_cast<float4*>(out) + (size_t)row * HW4_;

    // pre-sync: x is independent of the gate — start streaming immediately
    float4 v[16];
    #pragma unroll
    for (int i = 0; i < 16; ++i)
        v[i] = __ldcs(&x4[threadIdx.x + i * 256]);

    cudaGridDependencySynchronize();   // wait for k_gate

    float g = __ldg(&g_gate[row]);
    #pragma unroll
    for (int i = 0; i < 16; ++i) {
        float4 w = v[i];
        w.x *= g; w.y *= g; w.z *= g; w.w *= g;
        __stcs(&o4[threadIdx.x + i * 256], w);
    }
}

extern "C" void kernel_launch(void* const* d_in, const int* in_sizes, int n_in,
                              void* d_out, int out_size) {
    const float* x  = (const float*)d_in[0];
    const float* w1 = (const float*)d_in[1];
    const float* w2 = (const float*)d_in[2];
    const float* w3 = (const float*)d_in[3];
    const float* w4 = (const float*)d_in[4];
    const float* A2 = (const float*)d_in[5];
    float* out = (float*)d_out;

    // node 1: plain launch
    k_reduce<<<ROWS_, 256>>>(x);

    // node 2: PDL — may start during k_reduce; syncs internally
    {
        cudaLaunchConfig_t cfg = {};
        cfg.gridDim = dim3(B_);
        cfg.blockDim = dim3(256);
        cfg.stream = 0;
        cudaLaunchAttribute a[1];
        a[0].id = cudaLaunchAttributeProgrammaticStreamSerialization;
        a[0].val.programmaticStreamSerializationAllowed = 1;
        cfg.attrs = a;
        cfg.numAttrs = 1;
        cudaLaunchKernelEx(&cfg, k_gate, w1, w2, w3, w4, A2);
    }

    // node 3: PDL — may start during k_gate; syncs internally
    {
        cudaLaunchConfig_t cfg = {};
        cfg.gridDim = dim3(ROWS_);
        cfg.blockDim = dim3(256);
        cfg.stream = 0;
        cudaLaunchAttribute a[1];
        a[0].id = cudaLaunchAttributeProgrammaticStreamSerialization;
        a[0].val.programmaticStreamSerializationAllowed = 1;
        cfg.attrs = a;
        cfg.numAttrs = 1;
        cudaLaunchKernelEx(&cfg, k_scale, x, out);
    }
}